// round 5
// baseline (speedup 1.0000x reference)
#include <cuda_runtime.h>
#include <cstdint>

#define NLV 16
#define TSIZE (1u << 19)
#define HMASK (TSIZE - 1u)
#define PRIME1 2654435761u
#define PRIME2 805459861u

#define NMAX (1u << 20)
#define BINB 5                       // 5 bits per axis
#define BINRES (1 << BINB)           // 32
#define BINS (1 << (3 * BINB))       // 32768

__device__ unsigned g_hist[BINS];
__device__ unsigned g_cursor[BINS];
__device__ float4   g_xs[NMAX];      // xyz + original index packed in w

static __device__ __forceinline__ float2 lerp2(float2 a, float2 b, float w) {
    float u = 1.0f - w;
    return make_float2(a.x * u + b.x * w, a.y * u + b.y * w);
}

static __device__ __forceinline__ unsigned expand_bits5(unsigned v) {
    v &= 0x1Fu;
    v = (v | (v << 8)) & 0x100FFu;
    v = (v | (v << 4)) & 0x10C30C3u;
    v = (v | (v << 2)) & 0x1249249u;
    return v;
}

static __device__ __forceinline__ unsigned point_bin(float x0, float x1, float x2,
                                                     float bm0, float bm1, float bm2,
                                                     float bM0, float bM1, float bM2) {
    float u0 = (fminf(fmaxf(x0, bm0), bM0) - bm0) / (bM0 - bm0);
    float u1 = (fminf(fmaxf(x1, bm1), bM1) - bm1) / (bM1 - bm1);
    float u2 = (fminf(fmaxf(x2, bm2), bM2) - bm2) / (bM2 - bm2);
    unsigned i0 = min((unsigned)(u0 * (float)BINRES), (unsigned)(BINRES - 1));
    unsigned i1 = min((unsigned)(u1 * (float)BINRES), (unsigned)(BINRES - 1));
    unsigned i2 = min((unsigned)(u2 * (float)BINRES), (unsigned)(BINRES - 1));
    return expand_bits5(i0) | (expand_bits5(i1) << 1) | (expand_bits5(i2) << 2);
}

__global__ void zero_hist_kernel() {
    unsigned i = blockIdx.x * blockDim.x + threadIdx.x;
    if (i < BINS) g_hist[i] = 0u;
}

__global__ void __launch_bounds__(256)
hist_kernel(const float* __restrict__ x,
            const float* __restrict__ bmin,
            const float* __restrict__ bmax, unsigned n) {
    unsigned base = (blockIdx.x * blockDim.x + threadIdx.x) * 4u;
    float bm0 = __ldg(&bmin[0]), bm1 = __ldg(&bmin[1]), bm2 = __ldg(&bmin[2]);
    float bM0 = __ldg(&bmax[0]), bM1 = __ldg(&bmax[1]), bM2 = __ldg(&bmax[2]);
    float px[4][3];
    unsigned cnt = 0;
#pragma unroll
    for (int k = 0; k < 4; k++) {
        unsigned i = base + k;
        if (i < n) {
            px[k][0] = __ldg(&x[3 * (size_t)i + 0]);
            px[k][1] = __ldg(&x[3 * (size_t)i + 1]);
            px[k][2] = __ldg(&x[3 * (size_t)i + 2]);
            cnt = k + 1;
        }
    }
#pragma unroll
    for (int k = 0; k < 4; k++) {
        if ((unsigned)k < cnt) {
            unsigned b = point_bin(px[k][0], px[k][1], px[k][2],
                                   bm0, bm1, bm2, bM0, bM1, bM2);
            atomicAdd(&g_hist[b], 1u);
        }
    }
}

__global__ void scan_kernel() {
    __shared__ unsigned sp[1024];
    unsigned t = threadIdx.x;
    unsigned loc[32];
    unsigned s = 0;
#pragma unroll
    for (int k = 0; k < 32; k++) {
        loc[k] = s;
        s += g_hist[t * 32 + k];
    }
    sp[t] = s;
    __syncthreads();
    for (unsigned off = 1; off < 1024; off <<= 1) {
        unsigned add = (t >= off) ? sp[t - off] : 0u;
        __syncthreads();
        sp[t] += add;
        __syncthreads();
    }
    unsigned base = (t == 0) ? 0u : sp[t - 1];
#pragma unroll
    for (int k = 0; k < 32; k++)
        g_cursor[t * 32 + k] = base + loc[k];
}

__global__ void __launch_bounds__(256)
scatter_kernel(const float* __restrict__ x,
               const float* __restrict__ bmin,
               const float* __restrict__ bmax, unsigned n) {
    unsigned base = (blockIdx.x * blockDim.x + threadIdx.x) * 4u;
    float bm0 = __ldg(&bmin[0]), bm1 = __ldg(&bmin[1]), bm2 = __ldg(&bmin[2]);
    float bM0 = __ldg(&bmax[0]), bM1 = __ldg(&bmax[1]), bM2 = __ldg(&bmax[2]);
    float px[4][3];
    unsigned bin[4];
    unsigned cnt = 0;
#pragma unroll
    for (int k = 0; k < 4; k++) {
        unsigned i = base + k;
        if (i < n) {
            px[k][0] = __ldg(&x[3 * (size_t)i + 0]);
            px[k][1] = __ldg(&x[3 * (size_t)i + 1]);
            px[k][2] = __ldg(&x[3 * (size_t)i + 2]);
            cnt = k + 1;
        }
    }
#pragma unroll
    for (int k = 0; k < 4; k++)
        if ((unsigned)k < cnt)
            bin[k] = point_bin(px[k][0], px[k][1], px[k][2],
                               bm0, bm1, bm2, bM0, bM1, bM2);
    unsigned pos[4];
#pragma unroll
    for (int k = 0; k < 4; k++)
        if ((unsigned)k < cnt)
            pos[k] = atomicAdd(&g_cursor[bin[k]], 1u);
#pragma unroll
    for (int k = 0; k < 4; k++)
        if ((unsigned)k < cnt)
            g_xs[pos[k]] = make_float4(px[k][0], px[k][1], px[k][2],
                                       __uint_as_float(base + k));
}

__global__ void __launch_bounds__(256)
hashenc_kernel(const float2* __restrict__ emb,   // [16][2^19] float2
               const float* __restrict__ lw,     // [16]
               const float* __restrict__ bmin,   // [3]
               const float* __restrict__ bmax,   // [3]
               float* __restrict__ out,          // [N, 32]
               unsigned n)
{
    // floor(16 * b^i), b = exp((ln512 - ln16)/15) evaluated in float32 (numpy chain)
    const float RES[NLV] = {16.f, 20.f, 25.f, 32.f, 40.f, 50.f, 64.f, 80.f,
                            101.f, 128.f, 161.f, 203.f, 256.f, 322.f, 406.f, 512.f};

    __shared__ float sgate[NLV];
    if (threadIdx.x < NLV)
        sgate[threadIdx.x] = 1.0f / (1.0f + expf(-lw[threadIdx.x]));
    __syncthreads();

    unsigned j = blockIdx.x * blockDim.x + threadIdx.x;
    if (j >= n) return;

    float4 xp = g_xs[j];
    unsigned p = __float_as_uint(xp.w);   // original point index (output row)
    float x0 = xp.x, x1 = xp.y, x2 = xp.z;

    float bm0 = __ldg(&bmin[0]), bm1 = __ldg(&bmin[1]), bm2 = __ldg(&bmin[2]);
    float bM0 = __ldg(&bmax[0]), bM1 = __ldg(&bmax[1]), bM2 = __ldg(&bmax[2]);

    float xc0 = fminf(fmaxf(x0, bm0), bM0);
    float xc1 = fminf(fmaxf(x1, bm1), bM1);
    float xc2 = fminf(fmaxf(x2, bm2), bM2);

    float o[2 * NLV];

#pragma unroll
    for (int l = 0; l < NLV; l++) {
        float res = RES[l];
        float g0 = (bM0 - bm0) / res;
        float g1 = (bM1 - bm1) / res;
        float g2 = (bM2 - bm2) / res;
        float f0 = floorf((xc0 - bm0) / g0);
        float f1 = floorf((xc1 - bm1) / g1);
        float f2 = floorf((xc2 - bm2) / g2);
        float v0 = f0 * g0 + bm0;
        float v1 = f1 * g1 + bm1;
        float v2 = f2 * g2 + bm2;
        float wx = (x0 - v0) / ((v0 + g0) - v0);
        float wy = (x1 - v1) / ((v1 + g1) - v1);
        float wz = (x2 - v2) / ((v2 + g2) - v2);

        unsigned b0 = (unsigned)(int)f0;
        unsigned b1 = (unsigned)(int)f1;
        unsigned b2 = (unsigned)(int)f2;

        unsigned hx0 = b0;
        unsigned hx1 = b0 + 1u;
        unsigned hy0 = b1 * PRIME1;
        unsigned hy1 = (b1 + 1u) * PRIME1;
        unsigned hz0 = b2 * PRIME2;
        unsigned hz1 = (b2 + 1u) * PRIME2;

        const float2* tb = emb + (size_t)l * TSIZE;

        float2 e000, e001, e010, e011, e100, e101, e110, e111;
        if (l >= 11) {
            // fine levels: streaming (evict-first) — lines are touched once,
            // keep L1 capacity for the coarse levels the sort makes reusable
            e000 = __ldcs(&tb[(hx0 ^ hy0 ^ hz0) & HMASK]);
            e001 = __ldcs(&tb[(hx0 ^ hy0 ^ hz1) & HMASK]);
            e010 = __ldcs(&tb[(hx0 ^ hy1 ^ hz0) & HMASK]);
            e011 = __ldcs(&tb[(hx0 ^ hy1 ^ hz1) & HMASK]);
            e100 = __ldcs(&tb[(hx1 ^ hy0 ^ hz0) & HMASK]);
            e101 = __ldcs(&tb[(hx1 ^ hy0 ^ hz1) & HMASK]);
            e110 = __ldcs(&tb[(hx1 ^ hy1 ^ hz0) & HMASK]);
            e111 = __ldcs(&tb[(hx1 ^ hy1 ^ hz1) & HMASK]);
        } else {
            e000 = __ldg(&tb[(hx0 ^ hy0 ^ hz0) & HMASK]);
            e001 = __ldg(&tb[(hx0 ^ hy0 ^ hz1) & HMASK]);
            e010 = __ldg(&tb[(hx0 ^ hy1 ^ hz0) & HMASK]);
            e011 = __ldg(&tb[(hx0 ^ hy1 ^ hz1) & HMASK]);
            e100 = __ldg(&tb[(hx1 ^ hy0 ^ hz0) & HMASK]);
            e101 = __ldg(&tb[(hx1 ^ hy0 ^ hz1) & HMASK]);
            e110 = __ldg(&tb[(hx1 ^ hy1 ^ hz0) & HMASK]);
            e111 = __ldg(&tb[(hx1 ^ hy1 ^ hz1) & HMASK]);
        }

        float2 cx0 = lerp2(e000, e100, wx);
        float2 cx1 = lerp2(e001, e101, wx);
        float2 cx2 = lerp2(e010, e110, wx);
        float2 cx3 = lerp2(e011, e111, wx);
        float2 c0 = lerp2(cx0, cx2, wy);
        float2 c1 = lerp2(cx1, cx3, wy);
        float2 c  = lerp2(c0, c1, wz);

        float gate = sgate[l];
        o[2 * l + 0] = c.x * gate;
        o[2 * l + 1] = c.y * gate;
    }

    float4* o4 = reinterpret_cast<float4*>(out + (size_t)p * (2 * NLV));
#pragma unroll
    for (int q = 0; q < 8; q++)
        o4[q] = make_float4(o[4 * q + 0], o[4 * q + 1], o[4 * q + 2], o[4 * q + 3]);
}

extern "C" void kernel_launch(void* const* d_in, const int* in_sizes, int n_in,
                              void* d_out, int out_size) {
    const float*  x    = (const float*)d_in[0];
    const float2* emb  = (const float2*)d_in[1];
    const float*  lw   = (const float*)d_in[2];
    const float*  bmin = (const float*)d_in[3];
    const float*  bmax = (const float*)d_in[4];
    float* out = (float*)d_out;

    unsigned n = (unsigned)(in_sizes[0] / 3);

    zero_hist_kernel<<<(BINS + 255) / 256, 256>>>();
    hist_kernel<<<(n + 1023) / 1024, 256>>>(x, bmin, bmax, n);
    scan_kernel<<<1, 1024>>>();
    scatter_kernel<<<(n + 1023) / 1024, 256>>>(x, bmin, bmax, n);
    hashenc_kernel<<<(n + 255) / 256, 256>>>(emb, lw, bmin, bmax, out, n);
}

// round 6
// speedup vs baseline: 1.0691x; 1.0691x over previous
#include <cuda_runtime.h>
#include <cstdint>

#define NLV 16
#define TSIZE (1u << 19)
#define HMASK (TSIZE - 1u)
#define PRIME1 2654435761u
#define PRIME2 805459861u

#define NMAX (1u << 20)
#define BINB 5                       // 5 bits per axis
#define BINRES (1 << BINB)           // 32
#define BINS (1 << (3 * BINB))       // 32768

__device__ unsigned g_hist[BINS];
__device__ unsigned g_cursor[BINS];
__device__ float4   g_xs[NMAX];      // xyz + original index packed in w

static __device__ __forceinline__ float2 lerp2(float2 a, float2 b, float w) {
    float u = 1.0f - w;
    return make_float2(a.x * u + b.x * w, a.y * u + b.y * w);
}

static __device__ __forceinline__ unsigned expand_bits5(unsigned v) {
    v &= 0x1Fu;
    v = (v | (v << 8)) & 0x100FFu;
    v = (v | (v << 4)) & 0x10C30C3u;
    v = (v | (v << 2)) & 0x1249249u;
    return v;
}

static __device__ __forceinline__ unsigned point_bin(float x0, float x1, float x2,
                                                     float bm0, float bm1, float bm2,
                                                     float bM0, float bM1, float bM2) {
    float u0 = (fminf(fmaxf(x0, bm0), bM0) - bm0) / (bM0 - bm0);
    float u1 = (fminf(fmaxf(x1, bm1), bM1) - bm1) / (bM1 - bm1);
    float u2 = (fminf(fmaxf(x2, bm2), bM2) - bm2) / (bM2 - bm2);
    unsigned i0 = min((unsigned)(u0 * (float)BINRES), (unsigned)(BINRES - 1));
    unsigned i1 = min((unsigned)(u1 * (float)BINRES), (unsigned)(BINRES - 1));
    unsigned i2 = min((unsigned)(u2 * (float)BINRES), (unsigned)(BINRES - 1));
    return expand_bits5(i0) | (expand_bits5(i1) << 1) | (expand_bits5(i2) << 2);
}

// load 4 points (12 floats = 3 float4) for thread handling points base..base+3
static __device__ __forceinline__ void load4pts(const float4* __restrict__ x4,
                                                unsigned t, float px[4][3]) {
    float4 a0 = __ldg(&x4[3 * (size_t)t + 0]);   // x0 y0 z0 x1
    float4 a1 = __ldg(&x4[3 * (size_t)t + 1]);   // y1 z1 x2 y2
    float4 a2 = __ldg(&x4[3 * (size_t)t + 2]);   // z2 x3 y3 z3
    px[0][0] = a0.x; px[0][1] = a0.y; px[0][2] = a0.z;
    px[1][0] = a0.w; px[1][1] = a1.x; px[1][2] = a1.y;
    px[2][0] = a1.z; px[2][1] = a1.w; px[2][2] = a2.x;
    px[3][0] = a2.y; px[3][1] = a2.z; px[3][2] = a2.w;
}

__global__ void zero_hist_kernel() {
    unsigned i = blockIdx.x * blockDim.x + threadIdx.x;
    if (i < BINS) g_hist[i] = 0u;
}

__global__ void __launch_bounds__(256)
hist_kernel(const float* __restrict__ x,
            const float* __restrict__ bmin,
            const float* __restrict__ bmax, unsigned n) {
    unsigned t = blockIdx.x * blockDim.x + threadIdx.x;
    unsigned base = t * 4u;
    if (base >= n) return;
    float bm0 = __ldg(&bmin[0]), bm1 = __ldg(&bmin[1]), bm2 = __ldg(&bmin[2]);
    float bM0 = __ldg(&bmax[0]), bM1 = __ldg(&bmax[1]), bM2 = __ldg(&bmax[2]);
    float px[4][3];
    if (base + 4 <= n) {
        load4pts((const float4*)x, t, px);
        unsigned b0 = point_bin(px[0][0], px[0][1], px[0][2], bm0, bm1, bm2, bM0, bM1, bM2);
        unsigned b1 = point_bin(px[1][0], px[1][1], px[1][2], bm0, bm1, bm2, bM0, bM1, bM2);
        unsigned b2 = point_bin(px[2][0], px[2][1], px[2][2], bm0, bm1, bm2, bM0, bM1, bM2);
        unsigned b3 = point_bin(px[3][0], px[3][1], px[3][2], bm0, bm1, bm2, bM0, bM1, bM2);
        atomicAdd(&g_hist[b0], 1u);
        atomicAdd(&g_hist[b1], 1u);
        atomicAdd(&g_hist[b2], 1u);
        atomicAdd(&g_hist[b3], 1u);
    } else {
        for (unsigned i = base; i < n; i++) {
            float q0 = __ldg(&x[3 * (size_t)i + 0]);
            float q1 = __ldg(&x[3 * (size_t)i + 1]);
            float q2 = __ldg(&x[3 * (size_t)i + 2]);
            unsigned b = point_bin(q0, q1, q2, bm0, bm1, bm2, bM0, bM1, bM2);
            atomicAdd(&g_hist[b], 1u);
        }
    }
}

__global__ void scan_kernel() {
    __shared__ unsigned sp[1024];
    unsigned t = threadIdx.x;
    unsigned loc[32];
    unsigned s = 0;
#pragma unroll
    for (int k = 0; k < 32; k++) {
        loc[k] = s;
        s += g_hist[t * 32 + k];
    }
    sp[t] = s;
    __syncthreads();
    for (unsigned off = 1; off < 1024; off <<= 1) {
        unsigned add = (t >= off) ? sp[t - off] : 0u;
        __syncthreads();
        sp[t] += add;
        __syncthreads();
    }
    unsigned base = (t == 0) ? 0u : sp[t - 1];
#pragma unroll
    for (int k = 0; k < 32; k++)
        g_cursor[t * 32 + k] = base + loc[k];
}

__global__ void __launch_bounds__(256)
scatter_kernel(const float* __restrict__ x,
               const float* __restrict__ bmin,
               const float* __restrict__ bmax, unsigned n) {
    unsigned t = blockIdx.x * blockDim.x + threadIdx.x;
    unsigned base = t * 4u;
    if (base >= n) return;
    float bm0 = __ldg(&bmin[0]), bm1 = __ldg(&bmin[1]), bm2 = __ldg(&bmin[2]);
    float bM0 = __ldg(&bmax[0]), bM1 = __ldg(&bmax[1]), bM2 = __ldg(&bmax[2]);
    if (base + 4 <= n) {
        float px[4][3];
        load4pts((const float4*)x, t, px);
        unsigned bin[4], pos[4];
#pragma unroll
        for (int k = 0; k < 4; k++)
            bin[k] = point_bin(px[k][0], px[k][1], px[k][2],
                               bm0, bm1, bm2, bM0, bM1, bM2);
#pragma unroll
        for (int k = 0; k < 4; k++)
            pos[k] = atomicAdd(&g_cursor[bin[k]], 1u);
#pragma unroll
        for (int k = 0; k < 4; k++)
            g_xs[pos[k]] = make_float4(px[k][0], px[k][1], px[k][2],
                                       __uint_as_float(base + k));
    } else {
        for (unsigned i = base; i < n; i++) {
            float q0 = __ldg(&x[3 * (size_t)i + 0]);
            float q1 = __ldg(&x[3 * (size_t)i + 1]);
            float q2 = __ldg(&x[3 * (size_t)i + 2]);
            unsigned b = point_bin(q0, q1, q2, bm0, bm1, bm2, bM0, bM1, bM2);
            unsigned pos = atomicAdd(&g_cursor[b], 1u);
            g_xs[pos] = make_float4(q0, q1, q2, __uint_as_float(i));
        }
    }
}

__global__ void __launch_bounds__(256)
hashenc_kernel(const float2* __restrict__ emb,   // [16][2^19] float2
               const float* __restrict__ lw,     // [16]
               const float* __restrict__ bmin,   // [3]
               const float* __restrict__ bmax,   // [3]
               float* __restrict__ out,          // [N, 32]
               unsigned n)
{
    // floor(16 * b^i), b = exp((ln512 - ln16)/15) evaluated in float32 (numpy chain)
    const float RES[NLV] = {16.f, 20.f, 25.f, 32.f, 40.f, 50.f, 64.f, 80.f,
                            101.f, 128.f, 161.f, 203.f, 256.f, 322.f, 406.f, 512.f};

    __shared__ float sgate[NLV];
    if (threadIdx.x < NLV)
        sgate[threadIdx.x] = 1.0f / (1.0f + expf(-lw[threadIdx.x]));
    __syncthreads();

    unsigned j = blockIdx.x * blockDim.x + threadIdx.x;
    if (j >= n) return;

    float4 xp = g_xs[j];
    unsigned p = __float_as_uint(xp.w);   // original point index (output row)
    float x0 = xp.x, x1 = xp.y, x2 = xp.z;

    float bm0 = __ldg(&bmin[0]), bm1 = __ldg(&bmin[1]), bm2 = __ldg(&bmin[2]);
    float bM0 = __ldg(&bmax[0]), bM1 = __ldg(&bmax[1]), bM2 = __ldg(&bmax[2]);

    float xc0 = fminf(fmaxf(x0, bm0), bM0);
    float xc1 = fminf(fmaxf(x1, bm1), bM1);
    float xc2 = fminf(fmaxf(x2, bm2), bM2);

    float o[2 * NLV];

#pragma unroll
    for (int l = 0; l < NLV; l++) {
        float res = RES[l];
        float g0 = (bM0 - bm0) / res;
        float g1 = (bM1 - bm1) / res;
        float g2 = (bM2 - bm2) / res;
        float f0 = floorf((xc0 - bm0) / g0);
        float f1 = floorf((xc1 - bm1) / g1);
        float f2 = floorf((xc2 - bm2) / g2);
        float v0 = f0 * g0 + bm0;
        float v1 = f1 * g1 + bm1;
        float v2 = f2 * g2 + bm2;
        float wx = (x0 - v0) / ((v0 + g0) - v0);
        float wy = (x1 - v1) / ((v1 + g1) - v1);
        float wz = (x2 - v2) / ((v2 + g2) - v2);

        unsigned b0 = (unsigned)(int)f0;
        unsigned b1 = (unsigned)(int)f1;
        unsigned b2 = (unsigned)(int)f2;

        unsigned hx0 = b0;
        unsigned hx1 = b0 + 1u;
        unsigned hy0 = b1 * PRIME1;
        unsigned hy1 = (b1 + 1u) * PRIME1;
        unsigned hz0 = b2 * PRIME2;
        unsigned hz1 = (b2 + 1u) * PRIME2;

        const float2* tb = emb + (size_t)l * TSIZE;

        float2 e000 = __ldg(&tb[(hx0 ^ hy0 ^ hz0) & HMASK]);
        float2 e001 = __ldg(&tb[(hx0 ^ hy0 ^ hz1) & HMASK]);
        float2 e010 = __ldg(&tb[(hx0 ^ hy1 ^ hz0) & HMASK]);
        float2 e011 = __ldg(&tb[(hx0 ^ hy1 ^ hz1) & HMASK]);
        float2 e100 = __ldg(&tb[(hx1 ^ hy0 ^ hz0) & HMASK]);
        float2 e101 = __ldg(&tb[(hx1 ^ hy0 ^ hz1) & HMASK]);
        float2 e110 = __ldg(&tb[(hx1 ^ hy1 ^ hz0) & HMASK]);
        float2 e111 = __ldg(&tb[(hx1 ^ hy1 ^ hz1) & HMASK]);

        float2 cx0 = lerp2(e000, e100, wx);
        float2 cx1 = lerp2(e001, e101, wx);
        float2 cx2 = lerp2(e010, e110, wx);
        float2 cx3 = lerp2(e011, e111, wx);
        float2 c0 = lerp2(cx0, cx2, wy);
        float2 c1 = lerp2(cx1, cx3, wy);
        float2 c  = lerp2(c0, c1, wz);

        float gate = sgate[l];
        o[2 * l + 0] = c.x * gate;
        o[2 * l + 1] = c.y * gate;
    }

    float4* o4 = reinterpret_cast<float4*>(out + (size_t)p * (2 * NLV));
#pragma unroll
    for (int q = 0; q < 8; q++)
        o4[q] = make_float4(o[4 * q + 0], o[4 * q + 1], o[4 * q + 2], o[4 * q + 3]);
}

extern "C" void kernel_launch(void* const* d_in, const int* in_sizes, int n_in,
                              void* d_out, int out_size) {
    const float*  x    = (const float*)d_in[0];
    const float2* emb  = (const float2*)d_in[1];
    const float*  lw   = (const float*)d_in[2];
    const float*  bmin = (const float*)d_in[3];
    const float*  bmax = (const float*)d_in[4];
    float* out = (float*)d_out;

    unsigned n = (unsigned)(in_sizes[0] / 3);
    unsigned t4 = (n + 3) / 4;

    zero_hist_kernel<<<(BINS + 255) / 256, 256>>>();
    hist_kernel<<<(t4 + 255) / 256, 256>>>(x, bmin, bmax, n);
    scan_kernel<<<1, 1024>>>();
    scatter_kernel<<<(t4 + 255) / 256, 256>>>(x, bmin, bmax, n);
    hashenc_kernel<<<(n + 255) / 256, 256>>>(emb, lw, bmin, bmax, out, n);
}